// round 4
// baseline (speedup 1.0000x reference)
#include <cuda_runtime.h>
#include <cuda_bf16.h>
#include <cstdint>
#include <cstddef>

namespace {

constexpr int Nc = 16384, Kc = 32, Dc = 64;
constexpr int POINTS = 4 * Nc;           // 65536
constexpr int NTHR   = 128;              // 4 warps / CTA
constexpr int NCTA   = 296;              // 2 CTAs / SM, one full wave

// ---- shared memory layout (byte offsets) ----
constexpr int SM_BFRAG = 0;              // B'' fragment staging: 12*8*32*8 = 24576 B (init only)
constexpr int SM_W1    = 24576;          // 3*64 f32
constexpr int SM_B1    = 25344;          // 64 f32
constexpr int SM_WARP  = 25600;          // 4 per-warp regions
constexpr int PW       = 9472;           // per-warp: H [32x256B] / Gs [32x288B] overlay
constexpr int SMEM_BYTES = SM_WARP + 4 * PW;   // 63488

__device__ __forceinline__ uint32_t smem_u32(const void* p) {
    uint32_t a;
    asm("{ .reg .u64 t; cvta.to.shared.u64 t, %1; cvt.u32.u64 %0, t; }" : "=r"(a) : "l"(p));
    return a;
}
__device__ __forceinline__ uint32_t prmt_hi(uint32_t u0, uint32_t u1) {
    uint32_t d;  // low16 = top16(u0), high16 = top16(u1)
    asm("prmt.b32 %0, %1, %2, 0x7632;" : "=r"(d) : "r"(u0), "r"(u1));
    return d;
}
__device__ __forceinline__ uint32_t cvt_bf16x2(float hi_val, float lo_val) {
    uint32_t d;  // packs {upper = hi_val, lower = lo_val}
    asm("cvt.rn.bf16x2.f32 %0, %1, %2;" : "=r"(d) : "f"(hi_val), "f"(lo_val));
    return d;
}
__device__ __forceinline__ void mma_bf16(float* c, const uint32_t* a,
                                         uint32_t b0, uint32_t b1) {
    asm volatile(
        "mma.sync.aligned.m16n8k16.row.col.f32.bf16.bf16.f32 "
        "{%0,%1,%2,%3}, {%4,%5,%6,%7}, {%8,%9}, {%0,%1,%2,%3};"
        : "+f"(c[0]), "+f"(c[1]), "+f"(c[2]), "+f"(c[3])
        : "r"(a[0]), "r"(a[1]), "r"(a[2]), "r"(a[3]), "r"(b0), "r"(b1));
}

} // namespace

__global__ void __launch_bounds__(NTHR, 2) pc_mma_kernel(
    const float* __restrict__ x,      // [B, N, 64]
    const float* __restrict__ pos,    // [B, N, 3]
    const int*   __restrict__ nidx,   // [B, N, 32]
    const float* __restrict__ W1,     // [3, 64]
    const float* __restrict__ b1,     // [64]
    const float* __restrict__ W2,     // [64, 64]  (g-major: W2[g*64+f])
    const float* __restrict__ b2,     // [64]
    float*       __restrict__ out)    // [B, N, 64]
{
    extern __shared__ char smem[];
    const uint32_t sb = smem_u32(smem);

    const int tid  = threadIdx.x;
    const int warp = tid >> 5;
    const int lane = tid & 31;
    const int f0   = 2 * lane;

    // ================= one-time init =================
    float* w1s = (float*)(smem + SM_W1);
    float* b1s = (float*)(smem + SM_B1);
    for (int i = tid; i < 3 * Dc; i += NTHR) w1s[i] = W1[i];
    for (int i = tid; i < Dc; i += NTHR)     b1s[i] = b1[i];

    // B'' fragment staging table: built once in smem (only segs 0-3 = hi and
    // 8-11 = lo are consumed below; 4-7 duplicate hi and are skipped).
    for (int i = tid; i < 12 * 8 * 32; i += NTHR) {
        const int ks = i >> 8, ni = (i >> 5) & 7, ln = i & 31;
        const int n  = ni * 8 + (ln >> 2);
        const int k0 = (ks & 3) * 16 + (ln & 3) * 2;
        const bool lo = (ks >= 8);
        uint2 bf;
        {
            const float v0 = W2[k0 * Dc + n],       v1 = W2[(k0 + 1) * Dc + n];
            const float v2 = W2[(k0 + 8) * Dc + n], v3 = W2[(k0 + 9) * Dc + n];
            const uint32_t u0 = __float_as_uint(v0), u1 = __float_as_uint(v1);
            const uint32_t u2 = __float_as_uint(v2), u3 = __float_as_uint(v3);
            if (!lo) {
                bf.x = (u0 >> 16) | (u1 & 0xFFFF0000u);
                bf.y = (u2 >> 16) | (u3 & 0xFFFF0000u);
            } else {
                const float l0 = v0 - __uint_as_float(u0 & 0xFFFF0000u);
                const float l1 = v1 - __uint_as_float(u1 & 0xFFFF0000u);
                const float l2 = v2 - __uint_as_float(u2 & 0xFFFF0000u);
                const float l3 = v3 - __uint_as_float(u3 & 0xFFFF0000u);
                bf.x = cvt_bf16x2(l1, l0);
                bf.y = cvt_bf16x2(l3, l2);
            }
        }
        *(uint2*)(smem + SM_BFRAG + (size_t)i * 8) = bf;
    }
    __syncthreads();

    // ---- pull this lane's W2 fragments into REGISTERS (loop-invariant) ----
    // w2r[(seg*8 + ni)*2 + {0,1}]; seg 0-3 = hi planes, seg 4-7 = lo planes.
    uint32_t w2r[128];
#pragma unroll
    for (int s = 0; s < 4; ++s) {
#pragma unroll
        for (int ni = 0; ni < 8; ++ni) {
            const uint2 vh = *(const uint2*)(smem + SM_BFRAG +
                                             (size_t)((s * 8 + ni) * 32 + lane) * 8);
            const uint2 vl = *(const uint2*)(smem + SM_BFRAG +
                                             (size_t)(((8 + s) * 8 + ni) * 32 + lane) * 8);
            w2r[(s * 8 + ni) * 2]           = vh.x;
            w2r[(s * 8 + ni) * 2 + 1]       = vh.y;
            w2r[((4 + s) * 8 + ni) * 2]     = vl.x;
            w2r[((4 + s) * 8 + ni) * 2 + 1] = vl.y;
        }
    }

    // ================= per-lane constants =================
    const float b20 = b2[f0], b21 = b2[f0 + 1];
    char* const wb = smem + SM_WARP + warp * PW;
    const uint32_t wbase = sb + SM_WARP + warp * PW;

    const int rl  = lane & 7;            // swizzle key (= target row & 7)
    const int grp = lane >> 3;
    const int a_row = rl + (grp & 1) * 8;
    const int csel  = grp >> 1;
    const uint32_t a_addr0 = wbase + (uint32_t)a_row * 256u;
    const uint32_t a_addr1 = wbase + (uint32_t)(a_row + 16) * 256u;
    const int g = lane >> 2, t = lane & 3;

    // ================= per-point loop (one warp = one point) =================
    for (int p = blockIdx.x * 4 + warp; p < POINTS; p += NCTA * 4) {
        const int b = p >> 14;
        const int j = nidx[(size_t)p * Kc + lane];

        const float cx = pos[(size_t)p * 3 + 0];
        const float cy = pos[(size_t)p * 3 + 1];
        const float cz = pos[(size_t)p * 3 + 2];
        const float* npp = pos + (size_t)(b * Nc + j) * 3;
        const float rx = cx - npp[0], ry = cy - npp[1], rz = cz - npp[2];

        // ---- H build: lane = row k; hi chunks 0-7, lo chunks 8-15, swizzled ----
        {
            const uint32_t hrow = wbase + (uint32_t)lane * 256u;
#pragma unroll
            for (int c8 = 0; c8 < 8; ++c8) {
                uint32_t hq[4], lq[4];
#pragma unroll
                for (int h = 0; h < 2; ++h) {
                    const int g0 = c8 * 8 + h * 4;
                    const float4 a0 = *(const float4*)(w1s + g0);
                    const float4 a1 = *(const float4*)(w1s + Dc + g0);
                    const float4 a2 = *(const float4*)(w1s + 2 * Dc + g0);
                    const float4 bb = *(const float4*)(b1s + g0);
                    float z0 = fmaf(rx, a0.x, fmaf(ry, a1.x, fmaf(rz, a2.x, bb.x)));
                    float z1 = fmaf(rx, a0.y, fmaf(ry, a1.y, fmaf(rz, a2.y, bb.y)));
                    float z2 = fmaf(rx, a0.z, fmaf(ry, a1.z, fmaf(rz, a2.z, bb.z)));
                    float z3 = fmaf(rx, a0.w, fmaf(ry, a1.w, fmaf(rz, a2.w, bb.w)));
                    z0 = fmaxf(z0, 0.1f * z0);
                    z1 = fmaxf(z1, 0.1f * z1);
                    z2 = fmaxf(z2, 0.1f * z2);
                    z3 = fmaxf(z3, 0.1f * z3);
                    const uint32_t u0 = __float_as_uint(z0), u1 = __float_as_uint(z1);
                    const uint32_t u2 = __float_as_uint(z2), u3 = __float_as_uint(z3);
                    hq[2 * h]     = prmt_hi(u0, u1);
                    hq[2 * h + 1] = prmt_hi(u2, u3);
                    const float l0 = z0 - __uint_as_float(u0 & 0xFFFF0000u);
                    const float l1 = z1 - __uint_as_float(u1 & 0xFFFF0000u);
                    const float l2 = z2 - __uint_as_float(u2 & 0xFFFF0000u);
                    const float l3 = z3 - __uint_as_float(u3 & 0xFFFF0000u);
                    lq[2 * h]     = cvt_bf16x2(l1, l0);
                    lq[2 * h + 1] = cvt_bf16x2(l3, l2);
                }
                const uint32_t pc = (uint32_t)(c8 ^ rl);
                asm volatile("st.shared.v4.b32 [%0], {%1,%2,%3,%4};" ::
                             "r"(hrow + (pc << 4)),
                             "r"(hq[0]), "r"(hq[1]), "r"(hq[2]), "r"(hq[3]));
                asm volatile("st.shared.v4.b32 [%0], {%1,%2,%3,%4};" ::
                             "r"(hrow + ((8u + pc) << 4)),
                             "r"(lq[0]), "r"(lq[1]), "r"(lq[2]), "r"(lq[3]));
            }
        }
        __syncwarp();

        // ---- GEMM: G[32x64] = A''[32x192] * W2''(regs), 12 k16-steps ----
        float acc[64];
#pragma unroll
        for (int i = 0; i < 64; ++i) acc[i] = 0.0f;

#pragma unroll
        for (int ks = 0; ks < 12; ++ks) {
            const uint32_t cl = ((ks >= 4 && ks < 8) ? 8u : 0u)
                              + (uint32_t)(ks & 3) * 2u + (uint32_t)csel;
            const uint32_t coff = ((cl ^ (uint32_t)rl) << 4);
            uint32_t a0[4], a1[4];
            asm volatile("ldmatrix.sync.aligned.m8n8.x4.shared.b16 {%0,%1,%2,%3}, [%4];"
                         : "=r"(a0[0]), "=r"(a0[1]), "=r"(a0[2]), "=r"(a0[3])
                         : "r"(a_addr0 + coff));
            asm volatile("ldmatrix.sync.aligned.m8n8.x4.shared.b16 {%0,%1,%2,%3}, [%4];"
                         : "=r"(a1[0]), "=r"(a1[1]), "=r"(a1[2]), "=r"(a1[3])
                         : "r"(a_addr1 + coff));
            // B segment: ks 0-3 -> hi segs 0-3; ks 4-7 -> hi segs 0-3 again
            // (A lo plane); ks 8-11 -> lo segs 4-7 (A hi plane again).
            const int bseg = (ks < 8) ? (ks & 3) : (4 + (ks & 3));
#pragma unroll
            for (int ni = 0; ni < 8; ++ni) {
                const uint32_t bv0 = w2r[(bseg * 8 + ni) * 2];
                const uint32_t bv1 = w2r[(bseg * 8 + ni) * 2 + 1];
                mma_bf16(&acc[ni * 8],     a0, bv0, bv1);
                mma_bf16(&acc[ni * 8 + 4], a1, bv0, bv1);
            }
        }

        // ---- transpose G to row-major Gs (stride 288 B), same warp region ----
#pragma unroll
        for (int ni = 0; ni < 8; ++ni) {
#pragma unroll
            for (int mi = 0; mi < 2; ++mi) {
                const float* c = &acc[ni * 8 + mi * 4];
                char* r0 = wb + (mi * 16 + g) * 288 + ni * 32 + t * 8;
                *(float2*)r0         = make_float2(c[0], c[1]);
                *(float2*)(r0 + 8 * 288) = make_float2(c[2], c[3]);
            }
        }
        __syncwarp();

        // ---- epilogue: out[f] = sum_k (G[k,f] + b2[f]) * x[j_k, f] ----
        const float* xb = x + (size_t)b * Nc * Dc;
        float o0 = 0.0f, o1 = 0.0f;
#pragma unroll
        for (int kb = 0; kb < 4; ++kb) {
            float2 xv[8];
#pragma unroll
            for (int u = 0; u < 8; ++u) {
                const int jk = __shfl_sync(0xFFFFFFFFu, j, kb * 8 + u);
                xv[u] = *(const float2*)(xb + (size_t)jk * Dc + f0);
            }
#pragma unroll
            for (int u = 0; u < 8; ++u) {
                const float2 g2 = *(const float2*)(wb + (kb * 8 + u) * 288 + lane * 8);
                o0 = fmaf(g2.x + b20, xv[u].x, o0);
                o1 = fmaf(g2.y + b21, xv[u].y, o1);
            }
        }
        __syncwarp();   // Gs region reused as H next iteration

        *(float2*)(out + (size_t)p * Dc + f0) = make_float2(o0, o1);
    }
}

extern "C" void kernel_launch(void* const* d_in, const int* in_sizes, int n_in,
                              void* d_out, int out_size) {
    const float* x    = (const float*)d_in[0];
    const float* pos  = (const float*)d_in[1];
    const int*   nidx = (const int*)  d_in[2];
    const float* W1   = (const float*)d_in[3];
    const float* b1   = (const float*)d_in[4];
    const float* W2   = (const float*)d_in[5];
    const float* b2   = (const float*)d_in[6];
    float* out = (float*)d_out;
    (void)in_sizes; (void)n_in; (void)out_size;

    cudaFuncSetAttribute(pc_mma_kernel, cudaFuncAttributeMaxDynamicSharedMemorySize,
                         SMEM_BYTES);
    pc_mma_kernel<<<NCTA, NTHR, SMEM_BYTES>>>(x, pos, nidx, W1, b1, W2, b2, out);
}